// round 12
// baseline (speedup 1.0000x reference)
#include <cuda_runtime.h>
#include <cstdint>

#define NC     10
#define HC     16
#define HH     256
#define WW     256
#define BB     8
#define NSTEPS 10
#define PLANE  (HH*WW)          // 65536

// ---------------------------------------------------------------------------
// Device scratch (static __device__ arrays: allowed; no runtime allocation)
// ---------------------------------------------------------------------------
__device__ __align__(16) float g_Fx[BB*HC*PLANE];      // folded-perceive x-part + bias
__device__ __align__(16) float g_Tx[BB*HC*PLANE];      // tau x-part + tau_b + b_tau
__device__ __align__(16) float g_state[2][BB*HC*PLANE];
__device__ __align__(16) float g_delta[BB*HC*PLANE];

__device__ __align__(16) float g_Wfs[HC*HC*9];  // folded perceive, state channels [h][c][tap]
__device__ __align__(16) float g_Wfx[HC*NC*9];  // folded perceive, x channels
__device__ __align__(16) float g_bf[HC];
__device__ __align__(16) float g_Wts[HC*HC*9];  // tau: state channels
__device__ __align__(16) float g_Wtd[HC*HC*9];  // tau: delta channels
__device__ __align__(16) float g_Wtx[HC*NC*9];  // tau: x channels
__device__ __align__(16) float g_bt[HC];

// ---------------------------------------------------------------------------
// Weight folding:  Wf = update1_w @ perceive_w ; bf = update1_w @ perceive_b + update1_b
// Splits tau_w into x/state/delta channel groups; folds tau_b + b_tau.
// ---------------------------------------------------------------------------
__global__ void prep_weights_kernel(const float* __restrict__ pw,  const float* __restrict__ pb,
                                    const float* __restrict__ u1w, const float* __restrict__ u1b,
                                    const float* __restrict__ tw,  const float* __restrict__ tb,
                                    const float* __restrict__ btau)
{
    const int tid = threadIdx.x;
    // folded perceive: [16][26][9], 32-deep reduction
    for (int idx = tid; idx < HC*26*9; idx += blockDim.x) {
        int h = idx / (26*9);
        int rem = idx - h*(26*9);
        int c = rem / 9;
        int k = rem - c*9;
        float s = 0.f;
        #pragma unroll 4
        for (int p = 0; p < 32; p++)
            s += u1w[h*32 + p] * pw[(p*26 + c)*9 + k];
        if (c < NC) g_Wfx[(h*NC + c)*9 + k] = s;
        else        g_Wfs[(h*HC + (c-NC))*9 + k] = s;
    }
    for (int h = tid; h < HC; h += blockDim.x) {
        float s = u1b[h];
        for (int p = 0; p < 32; p++) s += u1w[h*32 + p] * pb[p];
        g_bf[h] = s;
        g_bt[h] = tb[h] + btau[h];
    }
    // tau weight split: tau_w is [16][42][3][3]
    for (int idx = tid; idx < HC*42*9; idx += blockDim.x) {
        int t = idx / (42*9);
        int rem = idx - t*(42*9);
        int c = rem / 9;
        int k = rem - c*9;
        float w = tw[idx];
        if (c < NC)          g_Wtx[(t*NC + c)*9 + k] = w;
        else if (c < NC+HC)  g_Wts[(t*HC + (c-NC))*9 + k] = w;
        else                 g_Wtd[(t*HC + (c-NC-HC))*9 + k] = w;
    }
}

__global__ void zero_state_kernel()
{
    int i = blockIdx.x*blockDim.x + threadIdx.x;   // over BB*HC*PLANE/4
    reinterpret_cast<float4*>(g_state[0])[i] = make_float4(0.f,0.f,0.f,0.f);
}

// ---------------------------------------------------------------------------
// Core: 3x3 conv accumulate over NIN input channels into acc[16][4].
// Block (16,16); each thread owns 4 consecutive W pixels. Tile 64x16 (+halo).
// Per-channel smem tile, double-buffered with register prefetch so the
// global-load latency of channel c+1 hides under compute of channel c.
// Zero padding at image borders (matches lax pad=1).
// (Exact R5 code shape — known-good codegen.)
// ---------------------------------------------------------------------------
#define TILE_ELEMS (18*66)

template<int NIN>
__device__ __forceinline__ void conv3x3_accum(float (&acc)[HC][4],
                                              const float* __restrict__ src,   // [NIN][H][W] (batch base)
                                              const float* __restrict__ sW,    // smem [HC][NIN][9]
                                              float* __restrict__ tile)        // smem 2*TILE_ELEMS
{
    const int tx  = threadIdx.x, ty = threadIdx.y;
    const int tid = ty*16 + tx;
    const int gx0 = blockIdx.x*64;
    const int gy0 = blockIdx.y*16;

    float pf[5];
    auto loadch = [&](int c) {
        const float* p = src + c*PLANE;
        #pragma unroll
        for (int i = 0; i < 5; i++) {
            int e = tid + i*256;
            float v = 0.f;
            if (e < TILE_ELEMS) {
                int r   = e / 66;
                int col = e - r*66;
                int gy = gy0 + r - 1;
                int gx = gx0 + col - 1;
                if (gy >= 0 && gy < HH && gx >= 0 && gx < WW)
                    v = __ldg(p + gy*WW + gx);
            }
            pf[i] = v;
        }
    };
    auto storech = [&](int b) {
        float* tb = tile + b*TILE_ELEMS;
        #pragma unroll
        for (int i = 0; i < 5; i++) {
            int e = tid + i*256;
            if (e < TILE_ELEMS) tb[e] = pf[i];
        }
    };

    loadch(0); storech(0); __syncthreads();

    #pragma unroll 1
    for (int c = 0; c < NIN; c++) {
        if (c + 1 < NIN) loadch(c + 1);          // prefetch next channel (LDG in flight)
        const float* tb = tile + (c & 1)*TILE_ELEMS;
        const float* wc = sW + c*9;              // layout [h][c][tap]: stride NIN*9 per h
        #pragma unroll
        for (int dy = 0; dy < 3; dy++) {
            const float* row = tb + (ty + dy)*66 + tx*4;
            float s0 = row[0], s1 = row[1], s2 = row[2],
                  s3 = row[3], s4 = row[4], s5 = row[5];
            #pragma unroll
            for (int h = 0; h < HC; h++) {
                const float* wh = wc + h*(NIN*9) + dy*3;
                float w0 = wh[0], w1 = wh[1], w2 = wh[2];
                acc[h][0] = fmaf(w0,s0, fmaf(w1,s1, fmaf(w2,s2, acc[h][0])));
                acc[h][1] = fmaf(w0,s1, fmaf(w1,s2, fmaf(w2,s3, acc[h][1])));
                acc[h][2] = fmaf(w0,s2, fmaf(w1,s3, fmaf(w2,s4, acc[h][2])));
                acc[h][3] = fmaf(w0,s3, fmaf(w1,s4, fmaf(w2,s5, acc[h][3])));
            }
        }
        if (c + 1 < NIN) {
            __syncthreads();                     // everyone done reading buf (c-1)&1
            storech((c + 1) & 1);
            __syncthreads();                     // next buffer visible
        }
    }
    __syncthreads();                             // tile reusable by caller
}

// ---------------------------------------------------------------------------
// Precompute F_x / T_x:  conv3x3 over the 10 x-channels, bias folded in.
// ---------------------------------------------------------------------------
__global__ void __launch_bounds__(256,3) conv_x_kernel(const float* __restrict__ x, int sel)
{
    __shared__ float sW[HC*NC*9];
    __shared__ float sb[HC];
    __shared__ float tile[2*TILE_ELEMS];

    const int tid = threadIdx.y*16 + threadIdx.x;
    const float* Wg   = sel ? g_Wtx : g_Wfx;
    const float* bg   = sel ? g_bt  : g_bf;
    float*       outg = sel ? g_Tx  : g_Fx;

    for (int i = tid; i < HC*NC*9; i += 256) sW[i] = Wg[i];
    if (tid < HC) sb[tid] = bg[tid];
    __syncthreads();

    const int bz = blockIdx.z;
    const int y  = blockIdx.y*16 + threadIdx.y;
    const int x0 = blockIdx.x*64 + threadIdx.x*4;

    float acc[HC][4];
    #pragma unroll
    for (int h = 0; h < HC; h++) {
        float b = sb[h];
        acc[h][0] = b; acc[h][1] = b; acc[h][2] = b; acc[h][3] = b;
    }

    conv3x3_accum<NC>(acc, x + bz*NC*PLANE, sW, tile);

    #pragma unroll
    for (int h = 0; h < HC; h++) {
        float4 v = make_float4(acc[h][0], acc[h][1], acc[h][2], acc[h][3]);
        *reinterpret_cast<float4*>(&outg[(bz*HC + h)*PLANE + y*WW + x0]) = v;
    }
}

// ---------------------------------------------------------------------------
// Step kernel A: hidden = relu(F_x + conv3x3(state, Wfs)); delta = W2@hidden + b2
// first!=0: state==0, skip the state conv (identical result).
// ---------------------------------------------------------------------------
__global__ void __launch_bounds__(256,3) step_a_kernel(int par, int first,
                                                       const float* __restrict__ u2w,
                                                       const float* __restrict__ u2b)
{
    __shared__ float sW[HC*HC*9];
    __shared__ float sW2[HC*HC];
    __shared__ float sb2[HC];
    __shared__ float tile[2*TILE_ELEMS];

    const int tid = threadIdx.y*16 + threadIdx.x;
    for (int i = tid; i < HC*HC*9; i += 256) sW[i] = g_Wfs[i];
    for (int i = tid; i < HC*HC;   i += 256) sW2[i] = u2w[i];
    if (tid < HC) sb2[tid] = u2b[tid];
    __syncthreads();

    const int bz = blockIdx.z;
    const int y  = blockIdx.y*16 + threadIdx.y;
    const int x0 = blockIdx.x*64 + threadIdx.x*4;

    float acc[HC][4];
    #pragma unroll
    for (int h = 0; h < HC; h++) {
        float4 v = *reinterpret_cast<const float4*>(&g_Fx[(bz*HC + h)*PLANE + y*WW + x0]);
        acc[h][0] = v.x; acc[h][1] = v.y; acc[h][2] = v.z; acc[h][3] = v.w;
    }

    if (!first) {
        const float* sin = g_state[par] + bz*HC*PLANE;
        conv3x3_accum<HC>(acc, sin, sW, tile);
    }

    #pragma unroll
    for (int h = 0; h < HC; h++) {
        acc[h][0] = fmaxf(acc[h][0], 0.f);
        acc[h][1] = fmaxf(acc[h][1], 0.f);
        acc[h][2] = fmaxf(acc[h][2], 0.f);
        acc[h][3] = fmaxf(acc[h][3], 0.f);
    }

    float* dl = g_delta + bz*HC*PLANE + y*WW + x0;
    #pragma unroll
    for (int d = 0; d < HC; d++) {
        float b = sb2[d];
        float o0 = b, o1 = b, o2 = b, o3 = b;
        #pragma unroll
        for (int h = 0; h < HC; h++) {
            float w = sW2[d*HC + h];
            o0 = fmaf(w, acc[h][0], o0);
            o1 = fmaf(w, acc[h][1], o1);
            o2 = fmaf(w, acc[h][2], o2);
            o3 = fmaf(w, acc[h][3], o3);
        }
        *reinterpret_cast<float4*>(dl + d*PLANE) = make_float4(o0, o1, o2, o3);
    }
}

// ---------------------------------------------------------------------------
// Step kernel B: z = T_x + conv3x3(state,Wts) + conv3x3(delta,Wtd);
// beta = clip(sigmoid(z), .01, .99); state' = beta*state + (1-beta)*delta
// first!=0: state==0, skip the state conv.
// ---------------------------------------------------------------------------
__global__ void __launch_bounds__(256,3) step_b_kernel(int par, int first)
{
    __shared__ float sW[2*HC*HC*9];
    __shared__ float tile[2*TILE_ELEMS];

    const int tid = threadIdx.y*16 + threadIdx.x;
    for (int i = tid; i < HC*HC*9; i += 256) {
        sW[i]            = g_Wts[i];
        sW[HC*HC*9 + i]  = g_Wtd[i];
    }
    __syncthreads();

    const int bz = blockIdx.z;
    const int y  = blockIdx.y*16 + threadIdx.y;
    const int x0 = blockIdx.x*64 + threadIdx.x*4;

    float acc[HC][4];
    #pragma unroll
    for (int h = 0; h < HC; h++) {
        float4 v = *reinterpret_cast<const float4*>(&g_Tx[(bz*HC + h)*PLANE + y*WW + x0]);
        acc[h][0] = v.x; acc[h][1] = v.y; acc[h][2] = v.z; acc[h][3] = v.w;
    }

    const float* sin = g_state[par] + bz*HC*PLANE;
    const float* din = g_delta      + bz*HC*PLANE;

    if (!first) conv3x3_accum<HC>(acc, sin, sW, tile);
    conv3x3_accum<HC>(acc, din, sW + HC*HC*9, tile);

    float* sout = g_state[1 - par] + bz*HC*PLANE + y*WW + x0;
    #pragma unroll
    for (int h = 0; h < HC; h++) {
        float4 sv = *reinterpret_cast<const float4*>(sin + h*PLANE + y*WW + x0);
        float4 dv = *reinterpret_cast<const float4*>(din + h*PLANE + y*WW + x0);
        float sa[4] = {sv.x, sv.y, sv.z, sv.w};
        float da[4] = {dv.x, dv.y, dv.z, dv.w};
        float o[4];
        #pragma unroll
        for (int j = 0; j < 4; j++) {
            float z = acc[h][j];
            float e = __expf(-z);
            float beta = __fdividef(1.f, 1.f + e);
            beta = fminf(fmaxf(beta, 0.01f), 0.99f);
            o[j] = fmaf(beta, sa[j] - da[j], da[j]);   // beta*s + (1-beta)*d
        }
        *reinterpret_cast<float4*>(sout + h*PLANE) = make_float4(o[0], o[1], o[2], o[3]);
    }
}

// ---------------------------------------------------------------------------
// Readout: out = conv1x1(state, readout_w) + readout_b
// ---------------------------------------------------------------------------
__global__ void readout_kernel(const float* __restrict__ rw, const float* __restrict__ rb,
                               float* __restrict__ out, int par)
{
    __shared__ float srw[NC*HC];
    __shared__ float srb[NC];
    const int tid = threadIdx.x;
    if (tid < NC*HC) srw[tid] = rw[tid];
    if (tid < NC)    srb[tid] = rb[tid];
    __syncthreads();

    int gid = blockIdx.x*blockDim.x + tid;          // over BB*PLANE/4
    int bz  = gid / (PLANE/4);
    int pp  = (gid - bz*(PLANE/4))*4;

    const float* st = g_state[par] + bz*HC*PLANE + pp;
    float4 sv[HC];
    #pragma unroll
    for (int h = 0; h < HC; h++)
        sv[h] = *reinterpret_cast<const float4*>(st + h*PLANE);

    float* op = out + bz*NC*PLANE + pp;
    #pragma unroll
    for (int n = 0; n < NC; n++) {
        float b = srb[n];
        float o0 = b, o1 = b, o2 = b, o3 = b;
        #pragma unroll
        for (int h = 0; h < HC; h++) {
            float w = srw[n*HC + h];
            o0 = fmaf(w, sv[h].x, o0);
            o1 = fmaf(w, sv[h].y, o1);
            o2 = fmaf(w, sv[h].z, o2);
            o3 = fmaf(w, sv[h].w, o3);
        }
        *reinterpret_cast<float4*>(op + n*PLANE) = make_float4(o0, o1, o2, o3);
    }
}

// ---------------------------------------------------------------------------
// Launch. Inputs (metadata order): x, perceive_w, perceive_b, update1_w,
// update1_b, update2_w, update2_b, tau_w, tau_b, b_tau, readout_w, readout_b,
// n_steps(int). n_steps is fixed at 10 for this problem shape.
// ---------------------------------------------------------------------------
extern "C" void kernel_launch(void* const* d_in, const int* in_sizes, int n_in,
                              void* d_out, int out_size)
{
    (void)in_sizes; (void)n_in; (void)out_size;
    const float* x    = (const float*)d_in[0];
    const float* pw   = (const float*)d_in[1];
    const float* pb   = (const float*)d_in[2];
    const float* u1w  = (const float*)d_in[3];
    const float* u1b  = (const float*)d_in[4];
    const float* u2w  = (const float*)d_in[5];
    const float* u2b  = (const float*)d_in[6];
    const float* tw   = (const float*)d_in[7];
    const float* tb   = (const float*)d_in[8];
    const float* btau = (const float*)d_in[9];
    const float* rw   = (const float*)d_in[10];
    const float* rb   = (const float*)d_in[11];
    float* out = (float*)d_out;

    dim3 cblk(16, 16);
    dim3 cgrid(WW/64, HH/16, BB);   // 4 x 16 x 8 = 512 blocks

    prep_weights_kernel<<<1, 256>>>(pw, pb, u1w, u1b, tw, tb, btau);
    zero_state_kernel<<<(BB*HC*PLANE/4)/256, 256>>>();
    conv_x_kernel<<<cgrid, cblk>>>(x, 0);   // g_Fx
    conv_x_kernel<<<cgrid, cblk>>>(x, 1);   // g_Tx

    int par = 0;
    for (int s = 0; s < NSTEPS; s++) {
        step_a_kernel<<<cgrid, cblk>>>(par, s == 0, u2w, u2b);
        step_b_kernel<<<cgrid, cblk>>>(par, s == 0);
        par ^= 1;
    }
    readout_kernel<<<(BB*PLANE/4)/256, 256>>>(rw, rb, out, par);
}

// round 15
// speedup vs baseline: 1.4414x; 1.4414x over previous
#include <cuda_runtime.h>
#include <cstdint>

#define NC     10
#define HC     16
#define HH     256
#define WW     256
#define BB     8
#define NSTEPS 10
#define PLANE  (HH*WW)          // 65536

// ---------------------------------------------------------------------------
// Device scratch (static __device__ arrays: allowed; no runtime allocation)
// ---------------------------------------------------------------------------
__device__ __align__(16) float g_Fx[BB*HC*PLANE];      // folded-perceive x-part + bias
__device__ __align__(16) float g_Tx[BB*HC*PLANE];      // tau x-part + tau_b + b_tau
__device__ __align__(16) float g_state[2][BB*HC*PLANE];
__device__ __align__(16) float g_delta[BB*HC*PLANE];

__device__ __align__(16) float g_Wfs[HC*HC*9];  // folded perceive, state channels [h][c][tap]
__device__ __align__(16) float g_Wfx[HC*NC*9];  // folded perceive, x channels
__device__ __align__(16) float g_bf[HC];
__device__ __align__(16) float g_Wts[HC*HC*9];  // tau: state channels
__device__ __align__(16) float g_Wtd[HC*HC*9];  // tau: delta channels
__device__ __align__(16) float g_Wtx[HC*NC*9];  // tau: x channels
__device__ __align__(16) float g_bt[HC];

// ---------------------------------------------------------------------------
// Weight folding:  Wf = update1_w @ perceive_w ; bf = update1_w @ perceive_b + update1_b
// Splits tau_w into x/state/delta channel groups; folds tau_b + b_tau.
// ---------------------------------------------------------------------------
__global__ void prep_weights_kernel(const float* __restrict__ pw,  const float* __restrict__ pb,
                                    const float* __restrict__ u1w, const float* __restrict__ u1b,
                                    const float* __restrict__ tw,  const float* __restrict__ tb,
                                    const float* __restrict__ btau)
{
    const int tid = threadIdx.x;
    // folded perceive: [16][26][9], 32-deep reduction
    for (int idx = tid; idx < HC*26*9; idx += blockDim.x) {
        int h = idx / (26*9);
        int rem = idx - h*(26*9);
        int c = rem / 9;
        int k = rem - c*9;
        float s = 0.f;
        #pragma unroll 4
        for (int p = 0; p < 32; p++)
            s += u1w[h*32 + p] * pw[(p*26 + c)*9 + k];
        if (c < NC) g_Wfx[(h*NC + c)*9 + k] = s;
        else        g_Wfs[(h*HC + (c-NC))*9 + k] = s;
    }
    for (int h = tid; h < HC; h += blockDim.x) {
        float s = u1b[h];
        for (int p = 0; p < 32; p++) s += u1w[h*32 + p] * pb[p];
        g_bf[h] = s;
        g_bt[h] = tb[h] + btau[h];
    }
    // tau weight split: tau_w is [16][42][3][3]
    for (int idx = tid; idx < HC*42*9; idx += blockDim.x) {
        int t = idx / (42*9);
        int rem = idx - t*(42*9);
        int c = rem / 9;
        int k = rem - c*9;
        float w = tw[idx];
        if (c < NC)          g_Wtx[(t*NC + c)*9 + k] = w;
        else if (c < NC+HC)  g_Wts[(t*HC + (c-NC))*9 + k] = w;
        else                 g_Wtd[(t*HC + (c-NC-HC))*9 + k] = w;
    }
}

// ---------------------------------------------------------------------------
// Core: 3x3 conv accumulate over NIN input channels into acc[16][4].
// Block (16,16); each thread owns 4 consecutive W pixels. Tile 64x16 (+halo).
// Per-channel smem tile, double-buffered with register prefetch so the
// global-load latency of channel c+1 hides under compute of channel c.
// Zero padding at image borders (matches lax pad=1).
// (Exact R5 code shape — known-good codegen. DO NOT PERTURB.)
// ---------------------------------------------------------------------------
#define TILE_ELEMS (18*66)

template<int NIN>
__device__ __forceinline__ void conv3x3_accum(float (&acc)[HC][4],
                                              const float* __restrict__ src,   // [NIN][H][W] (batch base)
                                              const float* __restrict__ sW,    // smem [HC][NIN][9]
                                              float* __restrict__ tile)        // smem 2*TILE_ELEMS
{
    const int tx  = threadIdx.x, ty = threadIdx.y;
    const int tid = ty*16 + tx;
    const int gx0 = blockIdx.x*64;
    const int gy0 = blockIdx.y*16;

    float pf[5];
    auto loadch = [&](int c) {
        const float* p = src + c*PLANE;
        #pragma unroll
        for (int i = 0; i < 5; i++) {
            int e = tid + i*256;
            float v = 0.f;
            if (e < TILE_ELEMS) {
                int r   = e / 66;
                int col = e - r*66;
                int gy = gy0 + r - 1;
                int gx = gx0 + col - 1;
                if (gy >= 0 && gy < HH && gx >= 0 && gx < WW)
                    v = __ldg(p + gy*WW + gx);
            }
            pf[i] = v;
        }
    };
    auto storech = [&](int b) {
        float* tb = tile + b*TILE_ELEMS;
        #pragma unroll
        for (int i = 0; i < 5; i++) {
            int e = tid + i*256;
            if (e < TILE_ELEMS) tb[e] = pf[i];
        }
    };

    loadch(0); storech(0); __syncthreads();

    #pragma unroll 1
    for (int c = 0; c < NIN; c++) {
        if (c + 1 < NIN) loadch(c + 1);          // prefetch next channel (LDG in flight)
        const float* tb = tile + (c & 1)*TILE_ELEMS;
        const float* wc = sW + c*9;              // layout [h][c][tap]: stride NIN*9 per h
        #pragma unroll
        for (int dy = 0; dy < 3; dy++) {
            const float* row = tb + (ty + dy)*66 + tx*4;
            float s0 = row[0], s1 = row[1], s2 = row[2],
                  s3 = row[3], s4 = row[4], s5 = row[5];
            #pragma unroll
            for (int h = 0; h < HC; h++) {
                const float* wh = wc + h*(NIN*9) + dy*3;
                float w0 = wh[0], w1 = wh[1], w2 = wh[2];
                acc[h][0] = fmaf(w0,s0, fmaf(w1,s1, fmaf(w2,s2, acc[h][0])));
                acc[h][1] = fmaf(w0,s1, fmaf(w1,s2, fmaf(w2,s3, acc[h][1])));
                acc[h][2] = fmaf(w0,s2, fmaf(w1,s3, fmaf(w2,s4, acc[h][2])));
                acc[h][3] = fmaf(w0,s3, fmaf(w1,s4, fmaf(w2,s5, acc[h][3])));
            }
        }
        if (c + 1 < NIN) {
            __syncthreads();                     // everyone done reading buf (c-1)&1
            storech((c + 1) & 1);
            __syncthreads();                     // next buffer visible
        }
    }
    __syncthreads();                             // tile reusable by caller
}

// ---------------------------------------------------------------------------
// Precompute F_x / T_x:  conv3x3 over the 10 x-channels, bias folded in.
// ---------------------------------------------------------------------------
__global__ void __launch_bounds__(256,2) conv_x_kernel(const float* __restrict__ x, int sel)
{
    __shared__ float sW[HC*NC*9];
    __shared__ float sb[HC];
    __shared__ float tile[2*TILE_ELEMS];

    const int tid = threadIdx.y*16 + threadIdx.x;
    const float* Wg   = sel ? g_Wtx : g_Wfx;
    const float* bg   = sel ? g_bt  : g_bf;
    float*       outg = sel ? g_Tx  : g_Fx;

    for (int i = tid; i < HC*NC*9; i += 256) sW[i] = Wg[i];
    if (tid < HC) sb[tid] = bg[tid];
    __syncthreads();

    const int bz = blockIdx.z;
    const int y  = blockIdx.y*16 + threadIdx.y;
    const int x0 = blockIdx.x*64 + threadIdx.x*4;

    float acc[HC][4];
    #pragma unroll
    for (int h = 0; h < HC; h++) {
        float b = sb[h];
        acc[h][0] = b; acc[h][1] = b; acc[h][2] = b; acc[h][3] = b;
    }

    conv3x3_accum<NC>(acc, x + bz*NC*PLANE, sW, tile);

    #pragma unroll
    for (int h = 0; h < HC; h++) {
        float4 v = make_float4(acc[h][0], acc[h][1], acc[h][2], acc[h][3]);
        *reinterpret_cast<float4*>(&outg[(bz*HC + h)*PLANE + y*WW + x0]) = v;
    }
}

// ---------------------------------------------------------------------------
// Step kernel A: hidden = relu(F_x + conv3x3(state, Wfs)); delta = W2@hidden + b2
// first!=0: state==0 -> skip the state conv (identical result).
// ---------------------------------------------------------------------------
__global__ void __launch_bounds__(256,2) step_a_kernel(int par, int first,
                                                       const float* __restrict__ u2w,
                                                       const float* __restrict__ u2b)
{
    __shared__ float sW[HC*HC*9];
    __shared__ float sW2[HC*HC];
    __shared__ float sb2[HC];
    __shared__ float tile[2*TILE_ELEMS];

    const int tid = threadIdx.y*16 + threadIdx.x;
    for (int i = tid; i < HC*HC*9; i += 256) sW[i] = g_Wfs[i];
    for (int i = tid; i < HC*HC;   i += 256) sW2[i] = u2w[i];
    if (tid < HC) sb2[tid] = u2b[tid];
    __syncthreads();

    const int bz = blockIdx.z;
    const int y  = blockIdx.y*16 + threadIdx.y;
    const int x0 = blockIdx.x*64 + threadIdx.x*4;

    float acc[HC][4];
    #pragma unroll
    for (int h = 0; h < HC; h++) {
        float4 v = *reinterpret_cast<const float4*>(&g_Fx[(bz*HC + h)*PLANE + y*WW + x0]);
        acc[h][0] = v.x; acc[h][1] = v.y; acc[h][2] = v.z; acc[h][3] = v.w;
    }

    if (!first) {
        const float* sin = g_state[par] + bz*HC*PLANE;
        conv3x3_accum<HC>(acc, sin, sW, tile);
    }

    #pragma unroll
    for (int h = 0; h < HC; h++) {
        acc[h][0] = fmaxf(acc[h][0], 0.f);
        acc[h][1] = fmaxf(acc[h][1], 0.f);
        acc[h][2] = fmaxf(acc[h][2], 0.f);
        acc[h][3] = fmaxf(acc[h][3], 0.f);
    }

    float* dl = g_delta + bz*HC*PLANE + y*WW + x0;
    #pragma unroll
    for (int d = 0; d < HC; d++) {
        float b = sb2[d];
        float o0 = b, o1 = b, o2 = b, o3 = b;
        #pragma unroll
        for (int h = 0; h < HC; h++) {
            float w = sW2[d*HC + h];
            o0 = fmaf(w, acc[h][0], o0);
            o1 = fmaf(w, acc[h][1], o1);
            o2 = fmaf(w, acc[h][2], o2);
            o3 = fmaf(w, acc[h][3], o3);
        }
        *reinterpret_cast<float4*>(dl + d*PLANE) = make_float4(o0, o1, o2, o3);
    }
}

// ---------------------------------------------------------------------------
// Step kernel B: z = T_x + conv3x3(state,Wts) + conv3x3(delta,Wtd);
// beta = clip(sigmoid(z), .01, .99); state' = beta*state + (1-beta)*delta
// first!=0: state==0 -> skip state conv, and use s=0 in the update.
// ---------------------------------------------------------------------------
__global__ void __launch_bounds__(256,2) step_b_kernel(int par, int first)
{
    __shared__ float sW[2*HC*HC*9];
    __shared__ float tile[2*TILE_ELEMS];

    const int tid = threadIdx.y*16 + threadIdx.x;
    for (int i = tid; i < HC*HC*9; i += 256) {
        sW[i]            = g_Wts[i];
        sW[HC*HC*9 + i]  = g_Wtd[i];
    }
    __syncthreads();

    const int bz = blockIdx.z;
    const int y  = blockIdx.y*16 + threadIdx.y;
    const int x0 = blockIdx.x*64 + threadIdx.x*4;

    float acc[HC][4];
    #pragma unroll
    for (int h = 0; h < HC; h++) {
        float4 v = *reinterpret_cast<const float4*>(&g_Tx[(bz*HC + h)*PLANE + y*WW + x0]);
        acc[h][0] = v.x; acc[h][1] = v.y; acc[h][2] = v.z; acc[h][3] = v.w;
    }

    const float* sin = g_state[par] + bz*HC*PLANE;
    const float* din = g_delta      + bz*HC*PLANE;

    if (!first) conv3x3_accum<HC>(acc, sin, sW, tile);
    conv3x3_accum<HC>(acc, din, sW + HC*HC*9, tile);

    float* sout = g_state[1 - par] + bz*HC*PLANE + y*WW + x0;
    #pragma unroll
    for (int h = 0; h < HC; h++) {
        float4 dv = *reinterpret_cast<const float4*>(din + h*PLANE + y*WW + x0);
        float da[4] = {dv.x, dv.y, dv.z, dv.w};
        float sa[4] = {0.f, 0.f, 0.f, 0.f};
        if (!first) {
            float4 sv = *reinterpret_cast<const float4*>(sin + h*PLANE + y*WW + x0);
            sa[0] = sv.x; sa[1] = sv.y; sa[2] = sv.z; sa[3] = sv.w;
        }
        float o[4];
        #pragma unroll
        for (int j = 0; j < 4; j++) {
            float z = acc[h][j];
            float e = __expf(-z);
            float beta = __fdividef(1.f, 1.f + e);
            beta = fminf(fmaxf(beta, 0.01f), 0.99f);
            o[j] = fmaf(beta, sa[j] - da[j], da[j]);   // beta*s + (1-beta)*d
        }
        *reinterpret_cast<float4*>(sout + h*PLANE) = make_float4(o[0], o[1], o[2], o[3]);
    }
}

// ---------------------------------------------------------------------------
// Readout: out = conv1x1(state, readout_w) + readout_b
// ---------------------------------------------------------------------------
__global__ void readout_kernel(const float* __restrict__ rw, const float* __restrict__ rb,
                               float* __restrict__ out, int par)
{
    __shared__ float srw[NC*HC];
    __shared__ float srb[NC];
    const int tid = threadIdx.x;
    if (tid < NC*HC) srw[tid] = rw[tid];
    if (tid < NC)    srb[tid] = rb[tid];
    __syncthreads();

    int gid = blockIdx.x*blockDim.x + tid;          // over BB*PLANE/4
    int bz  = gid / (PLANE/4);
    int pp  = (gid - bz*(PLANE/4))*4;

    const float* st = g_state[par] + bz*HC*PLANE + pp;
    float4 sv[HC];
    #pragma unroll
    for (int h = 0; h < HC; h++)
        sv[h] = *reinterpret_cast<const float4*>(st + h*PLANE);

    float* op = out + bz*NC*PLANE + pp;
    #pragma unroll
    for (int n = 0; n < NC; n++) {
        float b = srb[n];
        float o0 = b, o1 = b, o2 = b, o3 = b;
        #pragma unroll
        for (int h = 0; h < HC; h++) {
            float w = srw[n*HC + h];
            o0 = fmaf(w, sv[h].x, o0);
            o1 = fmaf(w, sv[h].y, o1);
            o2 = fmaf(w, sv[h].z, o2);
            o3 = fmaf(w, sv[h].w, o3);
        }
        *reinterpret_cast<float4*>(op + n*PLANE) = make_float4(o0, o1, o2, o3);
    }
}

// ---------------------------------------------------------------------------
// Launch. Inputs (metadata order): x, perceive_w, perceive_b, update1_w,
// update1_b, update2_w, update2_b, tau_w, tau_b, b_tau, readout_w, readout_b,
// n_steps(int). n_steps is fixed at 10 for this problem shape.
// NOTE: g_state[0] is never read (step 0 skips all state uses), so no zeroing
// kernel is needed.
// ---------------------------------------------------------------------------
extern "C" void kernel_launch(void* const* d_in, const int* in_sizes, int n_in,
                              void* d_out, int out_size)
{
    (void)in_sizes; (void)n_in; (void)out_size;
    const float* x    = (const float*)d_in[0];
    const float* pw   = (const float*)d_in[1];
    const float* pb   = (const float*)d_in[2];
    const float* u1w  = (const float*)d_in[3];
    const float* u1b  = (const float*)d_in[4];
    const float* u2w  = (const float*)d_in[5];
    const float* u2b  = (const float*)d_in[6];
    const float* tw   = (const float*)d_in[7];
    const float* tb   = (const float*)d_in[8];
    const float* btau = (const float*)d_in[9];
    const float* rw   = (const float*)d_in[10];
    const float* rb   = (const float*)d_in[11];
    float* out = (float*)d_out;

    dim3 cblk(16, 16);
    dim3 cgrid(WW/64, HH/16, BB);   // 4 x 16 x 8 = 512 blocks

    prep_weights_kernel<<<1, 256>>>(pw, pb, u1w, u1b, tw, tb, btau);
    conv_x_kernel<<<cgrid, cblk>>>(x, 0);   // g_Fx
    conv_x_kernel<<<cgrid, cblk>>>(x, 1);   // g_Tx

    int par = 0;
    for (int s = 0; s < NSTEPS; s++) {
        step_a_kernel<<<cgrid, cblk>>>(par, s == 0, u2w, u2b);
        step_b_kernel<<<cgrid, cblk>>>(par, s == 0);
        par ^= 1;
    }
    readout_kernel<<<(BB*PLANE/4)/256, 256>>>(rw, rb, out, par);
}